// round 1
// baseline (speedup 1.0000x reference)
#include <cuda_runtime.h>
#include <math.h>

// ---------------------------------------------------------------------------
// Fused IFS generator chain, fp32 SIMT baseline.
//   h  = relu(LN(z @ W1 + b1))
//   ya = silu(LN(h @ Wa + ba))
//   yb = LN(ya @ Wb + bb)
//   h2 = h + yb
//   x  = h2 @ Wout + bout
//   affines = clamp-SVD(x[:,:30]) ; probs = softmax(x[:,30:35])
// One CTA = 32 rows, all intermediates in smem (k-major, stride 33).
// ---------------------------------------------------------------------------

#define TB      32          // rows per CTA
#define THREADS 256
#define ST      33          // padded row stride in smem (k-major [col][row])

#define LATENT  256
#define MID     512
#define OUTW    35
#define NT      5
#define EPSV    1e-5f
#define THRESH  0.9f

// smem float layout
#define BUFF      (MID * ST)          // 16896 floats per activation buffer
#define SW_OFF    (3 * BUFF)          // weight staging: 8 x 512 = 4096 floats
#define SX_OFF    (SW_OFF + 4096)     // final x tile: 32 x 36
#define SMEM_F    (SX_OFF + TB * 36)  // 55936 floats = 223744 bytes

// ---------------------------------------------------------------------------
// GEMM: sOut[n][r] = sum_k sA[k][r] * W[k][n] + bias[n]   (N = 512 fixed)
// sA, sOut are k-major with stride ST. Weights staged 8 k-rows at a time.
// Thread tile: 8 rows x 8 cols (rows broadcast within warp -> free LDS).
// ---------------------------------------------------------------------------
__device__ __forceinline__ void gemm512(const float* __restrict__ sA, int K,
                                        const float* __restrict__ W,
                                        const float* __restrict__ bias,
                                        float* __restrict__ sOut,
                                        float* __restrict__ sW, int tid)
{
    const int r0 = (tid >> 6) * 8;        // row group (4 groups of 8)
    const int c0 = (tid & 63) * 8;        // col group (64 groups of 8)

    float acc[8][8];
#pragma unroll
    for (int i = 0; i < 8; i++)
#pragma unroll
        for (int j = 0; j < 8; j++) acc[i][j] = 0.f;

    for (int k0 = 0; k0 < K; k0 += 8) {
        __syncthreads();                  // previous sW fully consumed
        // stage W[k0:k0+8][0:512] -> sW (4096 floats, 4 float4 per thread)
#pragma unroll
        for (int it = 0; it < 4; it++) {
            int idx = tid + it * THREADS;         // 0..1023 (float4 index)
            int k  = idx >> 7;
            int f4 = idx & 127;
            *(float4*)&sW[k * 512 + f4 * 4] =
                *(const float4*)&W[(size_t)(k0 + k) * 512 + f4 * 4];
        }
        __syncthreads();

#pragma unroll
        for (int k = 0; k < 8; k++) {
            const float* ap = sA + (k0 + k) * ST + r0;
            float a[8];
#pragma unroll
            for (int i = 0; i < 8; i++) a[i] = ap[i];   // warp-broadcast LDS

            const float* wp = sW + k * 512 + c0;
            float4 w0 = *(const float4*)wp;
            float4 w1 = *(const float4*)(wp + 4);
            float w[8] = {w0.x, w0.y, w0.z, w0.w, w1.x, w1.y, w1.z, w1.w};

#pragma unroll
            for (int i = 0; i < 8; i++)
#pragma unroll
                for (int j = 0; j < 8; j++)
                    acc[i][j] = fmaf(a[i], w[j], acc[i][j]);
        }
    }
    __syncthreads();

#pragma unroll
    for (int j = 0; j < 8; j++) {
        float bj = bias[c0 + j];
#pragma unroll
        for (int i = 0; i < 8; i++)
            sOut[(c0 + j) * ST + r0 + i] = acc[i][j] + bj;
    }
}

// ---------------------------------------------------------------------------
// In-place layernorm over 512 cols of each row, then activation.
// act: 0 = none, 1 = relu, 2 = silu.  One warp handles 4 rows.
// ---------------------------------------------------------------------------
__device__ __forceinline__ void ln_act(float* __restrict__ sBuf,
                                       const float* __restrict__ g,
                                       const float* __restrict__ be,
                                       int act, int tid)
{
    __syncthreads();
    const int warp = tid >> 5, lane = tid & 31;
#pragma unroll
    for (int rr = 0; rr < 4; rr++) {
        const int r = warp * 4 + rr;
        float s = 0.f, s2 = 0.f;
        for (int c = lane; c < MID; c += 32) {
            float v = sBuf[c * ST + r];
            s += v; s2 += v * v;
        }
#pragma unroll
        for (int o = 16; o; o >>= 1) {
            s  += __shfl_xor_sync(0xffffffffu, s,  o);
            s2 += __shfl_xor_sync(0xffffffffu, s2, o);
        }
        const float mu   = s * (1.f / MID);
        const float var  = fmaxf(s2 * (1.f / MID) - mu * mu, 0.f);
        const float rstd = 1.f / sqrtf(var + EPSV);
        for (int c = lane; c < MID; c += 32) {
            float v = (sBuf[c * ST + r] - mu) * rstd * g[c] + be[c];
            if (act == 1)      v = fmaxf(v, 0.f);
            else if (act == 2) v = v * (1.f / (1.f + expf(-v)));
            sBuf[c * ST + r] = v;
        }
    }
    __syncthreads();
}

// ---------------------------------------------------------------------------
__global__ void __launch_bounds__(THREADS, 1)
ifs_kernel(const float* __restrict__ z,
           const float* __restrict__ W1, const float* __restrict__ b1,
           const float* __restrict__ g1, const float* __restrict__ be1,
           const float* __restrict__ Wa, const float* __restrict__ ba,
           const float* __restrict__ ga, const float* __restrict__ bea,
           const float* __restrict__ Wb, const float* __restrict__ bb,
           const float* __restrict__ gb, const float* __restrict__ beb,
           const float* __restrict__ Wout, const float* __restrict__ bout,
           float* __restrict__ out, int Btot)
{
    extern __shared__ float sm[];
    float* buf0 = sm;                 // z -> u -> yb -> h2
    float* buf1 = sm + BUFF;          // h
    float* buf2 = sm + 2 * BUFF;      // ya
    float* sW   = sm + SW_OFF;
    float* sX   = sm + SX_OFF;

    const int tid  = threadIdx.x;
    const int row0 = blockIdx.x * TB;

    // load z tile k-major into buf0
    for (int i = tid; i < TB * (LATENT / 4); i += THREADS) {
        int r  = i >> 6;              // 0..31
        int c4 = i & 63;              // 0..63 float4 within row
        float4 v = *(const float4*)&z[(size_t)(row0 + r) * LATENT + c4 * 4];
        buf0[(c4 * 4 + 0) * ST + r] = v.x;
        buf0[(c4 * 4 + 1) * ST + r] = v.y;
        buf0[(c4 * 4 + 2) * ST + r] = v.z;
        buf0[(c4 * 4 + 3) * ST + r] = v.w;
    }
    __syncthreads();

    gemm512(buf0, LATENT, W1, b1, buf1, sW, tid);   // h_pre
    ln_act(buf1, g1, be1, /*relu*/1, tid);          // h
    gemm512(buf1, MID, Wa, ba, buf2, sW, tid);      // ya_pre
    ln_act(buf2, ga, bea, /*silu*/2, tid);          // ya
    gemm512(buf2, MID, Wb, bb, buf0, sW, tid);      // u
    ln_act(buf0, gb, beb, /*none*/0, tid);          // yb

    // h2 = h + yb  (into buf0)
    for (int i = tid; i < MID * TB; i += THREADS) {
        int c = i >> 5, r = i & 31;
        buf0[c * ST + r] += buf1[c * ST + r];
    }
    __syncthreads();

    // x = h2 @ Wout + bout -> sX[r][j]  (35 cols, stride 36)
    {
        const int r = tid >> 3, jt = tid & 7;
        float acc[5] = {0.f, 0.f, 0.f, 0.f, 0.f};
        for (int k0 = 0; k0 < MID; k0 += 8) {
            __syncthreads();
            for (int i = tid; i < 8 * OUTW; i += THREADS) {
                int k = i / OUTW, n = i % OUTW;
                sW[k * 36 + n] = Wout[(size_t)(k0 + k) * OUTW + n];
            }
            __syncthreads();
#pragma unroll
            for (int k = 0; k < 8; k++) {
                float a = buf0[(k0 + k) * ST + r];
#pragma unroll
                for (int m = 0; m < 5; m++) {
                    int j = jt + 8 * m;
                    if (j < OUTW) acc[m] = fmaf(a, sW[k * 36 + j], acc[m]);
                }
            }
        }
        __syncthreads();
#pragma unroll
        for (int m = 0; m < 5; m++) {
            int j = jt + 8 * m;
            if (j < OUTW) sX[r * 36 + j] = acc[m] + bout[j];
        }
    }
    __syncthreads();

    // --- postprocess: per (row, transform) closed-form 2x2 SVD clamp ---
    // M = Q*Rot(a2) + R*Ref(a1); s1 = Q+R, s2 = Q-R. Clamping singular values
    // (s1 -> min(s1,t), s2 -> clamp(s2,-t,t)) == rescaling Q,R with fixed
    // rotation/reflection parts: M2 = rQ*[[E,-H],[H,E]] + rR*[[F,G],[G,-F]].
    if (tid < TB * NT) {
        const int r = tid / NT, t = tid % NT;
        const size_t gr = (size_t)(row0 + r);
        const float* xp = &sX[r * 36 + t * 6];
        float a = xp[0], b = xp[1], tx = xp[2];
        float c = xp[3], d = xp[4], ty = xp[5];

        float E = 0.5f * (a + d), F = 0.5f * (a - d);
        float G = 0.5f * (c + b), H = 0.5f * (c - b);
        float Q = sqrtf(E * E + H * H);
        float R = sqrtf(F * F + G * G);
        float s1 = Q + R, s2 = Q - R;
        float s1c = fminf(s1, THRESH);
        float s2c = fminf(fmaxf(s2, -THRESH), THRESH);
        float Qc = 0.5f * (s1c + s2c), Rc = 0.5f * (s1c - s2c);
        float rQ = Qc / fmaxf(Q, 1e-30f);
        float rR = Rc / fmaxf(R, 1e-30f);

        float na =  rQ * E + rR * F;
        float nb = -rQ * H + rR * G;
        float nc =  rQ * H + rR * G;
        float nd =  rQ * E - rR * F;

        float* op = out + (gr * NT + t) * 6;
        op[0] = na; op[1] = nb; op[2] = tx;
        op[3] = nc; op[4] = nd; op[5] = ty;
    }

    // --- softmax over 5 logits per row ---
    if (tid < TB) {
        const int r = tid;
        const size_t gr = (size_t)(row0 + r);
        float l[5], mx = -1e30f;
#pragma unroll
        for (int k = 0; k < 5; k++) { l[k] = sX[r * 36 + 30 + k]; mx = fmaxf(mx, l[k]); }
        float ssum = 0.f;
#pragma unroll
        for (int k = 0; k < 5; k++) { l[k] = expf(l[k] - mx); ssum += l[k]; }
        float inv = 1.f / ssum;
        float* op = out + (size_t)Btot * (NT * 6) + gr * NT;
#pragma unroll
        for (int k = 0; k < 5; k++) op[k] = l[k] * inv;
    }
}

// ---------------------------------------------------------------------------
extern "C" void kernel_launch(void* const* d_in, const int* in_sizes, int n_in,
                              void* d_out, int out_size)
{
    const float* z    = (const float*)d_in[0];
    const float* W1   = (const float*)d_in[1];
    const float* b1   = (const float*)d_in[2];
    const float* g1   = (const float*)d_in[3];
    const float* be1  = (const float*)d_in[4];
    const float* Wa   = (const float*)d_in[5];
    const float* ba   = (const float*)d_in[6];
    const float* ga   = (const float*)d_in[7];
    const float* bea  = (const float*)d_in[8];
    const float* Wb   = (const float*)d_in[9];
    const float* bb   = (const float*)d_in[10];
    const float* gb   = (const float*)d_in[11];
    const float* gbeb = (const float*)d_in[12];
    const float* Wout = (const float*)d_in[13];
    const float* bout = (const float*)d_in[14];
    float* out = (float*)d_out;

    const int Btot = in_sizes[0] / LATENT;
    const int smem_bytes = SMEM_F * sizeof(float);

    cudaFuncSetAttribute(ifs_kernel,
                         cudaFuncAttributeMaxDynamicSharedMemorySize, smem_bytes);

    ifs_kernel<<<Btot / TB, THREADS, smem_bytes>>>(
        z, W1, b1, g1, be1, Wa, ba, ga, bea, Wb, bb, gb, gbeb,
        Wout, bout, out, Btot);
}